// round 15
// baseline (speedup 1.0000x reference)
#include <cuda_runtime.h>
#include <cuda_fp16.h>
#include <math_constants.h>
#include <cstdint>
#include <cstddef>

#define BATCH 2
#define SEQ   4096
#define DIM   512
#define MT_SPLITK 16

// ---------------- scratch (allocation-free: __device__ globals) ----------------
__device__ __half g_qry_h[(size_t)BATCH * SEQ * DIM];
__device__ __half g_qry_l[(size_t)BATCH * SEQ * DIM];
__device__ __half g_key_h[(size_t)BATCH * SEQ * DIM];
__device__ __half g_key_l[(size_t)BATCH * SEQ * DIM];
__device__ __half g_wq_h[(size_t)DIM * DIM];
__device__ __half g_wq_l[(size_t)DIM * DIM];
__device__ __half g_wk_h[(size_t)DIM * DIM];
__device__ __half g_wk_l[(size_t)DIM * DIM];
__device__ float  g_mt_part[(size_t)MT_SPLITK * DIM * DIM];   // split-K partials
__device__ __half g_mt_h[(size_t)DIM * DIM];
__device__ __half g_mt_l[(size_t)DIM * DIM];
__device__ __half g_keyT_h[(size_t)BATCH * DIM * SEQ];
__device__ __half g_keyT_l[(size_t)BATCH * DIM * SEQ];
__device__ __half g_qm_h[(size_t)BATCH * SEQ * DIM];
__device__ __half g_qm_l[(size_t)BATCH * SEQ * DIM];
__device__ float  g_sc [(size_t)BATCH * SEQ * SEQ];
__device__ __half g_w_h[(size_t)BATCH * SEQ * SEQ];

// ---------------- helpers ----------------
__device__ __forceinline__ uint32_t s2u(const void* p) {
    uint32_t a;
    asm("{ .reg .u64 t; cvta.to.shared.u64 t, %1; cvt.u32.u64 %0, t; }" : "=r"(a) : "l"(p));
    return a;
}

__device__ __forceinline__ void ldsm_x4(uint32_t& r0, uint32_t& r1, uint32_t& r2, uint32_t& r3,
                                        uint32_t addr) {
    asm volatile("ldmatrix.sync.aligned.m8n8.x4.shared.b16 {%0,%1,%2,%3}, [%4];"
                 : "=r"(r0), "=r"(r1), "=r"(r2), "=r"(r3) : "r"(addr));
}

__device__ __forceinline__ void mma16816(float* d, const uint32_t* a, const uint32_t* b) {
    asm volatile(
        "mma.sync.aligned.m16n8k16.row.col.f32.f16.f16.f32 "
        "{%0,%1,%2,%3},{%4,%5,%6,%7},{%8,%9},{%0,%1,%2,%3};"
        : "+f"(d[0]), "+f"(d[1]), "+f"(d[2]), "+f"(d[3])
        : "r"(a[0]), "r"(a[1]), "r"(a[2]), "r"(a[3]), "r"(b[0]), "r"(b[1]));
}

__device__ __forceinline__ void split_h(float v, __half& h, __half& l) {
    h = __float2half_rn(v);
    l = __float2half_rn(v - __half2float(h));
}

// ---------------- prep kernels ----------------
// Fused, vectorized split of up to two tensors: grid.y selects tensor.
__global__ void __launch_bounds__(256) split2_kernel(
    const float* __restrict__ in0, __half* __restrict__ oh0, __half* __restrict__ ol0,
    const float* __restrict__ in1, __half* __restrict__ oh1, __half* __restrict__ ol1,
    size_t n4)
{
    const float* in = blockIdx.y ? in1 : in0;
    __half* oh = blockIdx.y ? oh1 : oh0;
    __half* ol = blockIdx.y ? ol1 : ol0;
    for (size_t i = (size_t)blockIdx.x * blockDim.x + threadIdx.x; i < n4;
         i += (size_t)gridDim.x * blockDim.x) {
        float4 v = *(const float4*)(in + i * 4);
        __half h0, l0, h1, l1, h2, l2, h3, l3;
        split_h(v.x, h0, l0); split_h(v.y, h1, l1);
        split_h(v.z, h2, l2); split_h(v.w, h3, l3);
        *(__half2*)(oh + i * 4)     = __halves2half2(h0, h1);
        *(__half2*)(oh + i * 4 + 2) = __halves2half2(h2, h3);
        *(__half2*)(ol + i * 4)     = __halves2half2(l0, l1);
        *(__half2*)(ol + i * 4 + 2) = __halves2half2(l2, l3);
    }
}

// sum MT_SPLITK fp32 partials -> exact fp16 split (vectorized by float4)
__global__ void __launch_bounds__(256) reduce_split_kernel(
    const float* __restrict__ part, __half* __restrict__ oh, __half* __restrict__ ol,
    size_t n, size_t n4)
{
    for (size_t i = (size_t)blockIdx.x * blockDim.x + threadIdx.x; i < n4;
         i += (size_t)gridDim.x * blockDim.x) {
        float4 s = *(const float4*)(part + i * 4);
        #pragma unroll
        for (int k = 1; k < MT_SPLITK; k++) {
            float4 v = *(const float4*)(part + (size_t)k * n + i * 4);
            s.x += v.x; s.y += v.y; s.z += v.z; s.w += v.w;
        }
        __half h0, l0, h1, l1, h2, l2, h3, l3;
        split_h(s.x, h0, l0); split_h(s.y, h1, l1);
        split_h(s.z, h2, l2); split_h(s.w, h3, l3);
        *(__half2*)(oh + i * 4)     = __halves2half2(h0, h1);
        *(__half2*)(oh + i * 4 + 2) = __halves2half2(h2, h3);
        *(__half2*)(ol + i * 4)     = __halves2half2(l0, l1);
        *(__half2*)(ol + i * 4 + 2) = __halves2half2(l2, l3);
    }
}

// Fused key prep: emits BOTH the straight split (sh/sl, [R,C]) and the
// transposed split (oh/ol, [C,R]) in one pass over the input.
__global__ void transpose_split_plus_kernel(
    const float* __restrict__ in,
    __half* __restrict__ oh, __half* __restrict__ ol,   // transposed [C,R]
    __half* __restrict__ sh, __half* __restrict__ sl,   // straight  [R,C]
    int R, int C, long long sIn, long long sOutT, long long sOutS)
{
    __shared__ float t[32][33];
    const int bz = blockIdx.z;
    in += (size_t)bz * sIn;
    oh += (size_t)bz * sOutT;
    ol += (size_t)bz * sOutT;
    sh += (size_t)bz * sOutS;
    sl += (size_t)bz * sOutS;
    const int c0 = blockIdx.x * 32, r0 = blockIdx.y * 32;
    const int tx = threadIdx.x, ty = threadIdx.y;  // 32 x 8
    #pragma unroll
    for (int j = 0; j < 32; j += 8) {
        size_t sidx = (size_t)(r0 + ty + j) * C + c0 + tx;
        float v = in[sidx];
        t[ty + j][tx] = v;
        __half h, l; split_h(v, h, l);
        sh[sidx] = h; sl[sidx] = l;              // coalesced along tx
    }
    __syncthreads();
    #pragma unroll
    for (int j = 0; j < 32; j += 8) {
        size_t idx = (size_t)(c0 + ty + j) * R + r0 + tx;
        __half h, l; split_h(t[tx][ty + j], h, l);
        oh[idx] = h; ol[idx] = l;
    }
}

// ---------------- mma.sync fp16 GEMM:  C[M,N] = A[M,K] * B[N,K]^T -------------
#define BM 256
#define BN 128
#define BK 32
#define STAGES 4
#define ATILE_B (BM * BK * 2)
#define BTILE_B (BN * BK * 2)
#define STAGE_B (2 * ATILE_B + 2 * BTILE_B)   // 48 KB
#define DYN_SMEM (STAGES * STAGE_B)           // 192 KB
#define NTHREADS 512

__device__ __forceinline__ uint32_t sw_off(int row, int ch) {
    return (uint32_t)(row * 64 + ((ch ^ ((row >> 1) & 3)) << 4));
}

template <int NPASS, int SPLITK = 1>
__global__ void __launch_bounds__(NTHREADS, 1) gemm_mma(
    const __half* __restrict__ Ah, const __half* __restrict__ Al,
    const __half* __restrict__ Bh, const __half* __restrict__ Bl,
    float* __restrict__ Cf, __half* __restrict__ Ch, __half* __restrict__ Cl,
    int M, int N, int K, long long sA, long long sB, long long sC)
{
    extern __shared__ char smem[];
    const int tid  = threadIdx.x;
    const int lane = tid & 31;
    const int wid  = tid >> 5;
    const int wm   = wid & 7;
    const int wn   = wid >> 3;
    const int bz = blockIdx.z;
    int kstart, klen;
    if (SPLITK > 1) {
        kstart = bz * (K / SPLITK);
        klen   = K / SPLITK;
        Cf += (size_t)bz * M * N;
    } else {
        kstart = 0;
        klen   = K;
        Ah += (size_t)bz * sA;
        Bh += (size_t)bz * sB;
        if (NPASS == 3) { Al += (size_t)bz * sA; Bl += (size_t)bz * sB; }
        if (Cf) Cf += (size_t)bz * sC;
        if (Ch) { Ch += (size_t)bz * sC; Cl += (size_t)bz * sC; }
    }
    const int bm = blockIdx.y * BM;
    const int bn = blockIdx.x * BN;
    const uint32_t sbase = s2u(smem);
    const int NC = klen / BK;

    float acc[2][8][4];
    #pragma unroll
    for (int a = 0; a < 2; a++)
        #pragma unroll
        for (int b = 0; b < 8; b++)
            #pragma unroll
            for (int c = 0; c < 4; c++) acc[a][b][c] = 0.0f;

    auto load_chunk = [&](int chunk) {
        const uint32_t sb = sbase + (chunk % STAGES) * STAGE_B;
        constexpr int J = (NPASS == 3) ? 6 : 3;
        #pragma unroll
        for (int j = 0; j < J; j++) {
            int g = tid + NTHREADS * j;
            const __half* base;
            uint32_t dst;
            int row, c;
            if (NPASS == 3) {
                if (g < 2048) {
                    int t = g >> 10;
                    int u = g & 1023;
                    row = u >> 2; c = u & 3;
                    base = t ? Al : Ah;
                    dst = sb + t * ATILE_B + sw_off(row, c);
                    base += (size_t)(bm + row) * K + kstart + chunk * BK + c * 8;
                } else {
                    int b2 = g - 2048;
                    int t = b2 >> 9;
                    int u = b2 & 511;
                    row = u >> 2; c = u & 3;
                    base = t ? Bl : Bh;
                    dst = sb + 2 * ATILE_B + t * BTILE_B + sw_off(row, c);
                    base += (size_t)(bn + row) * K + kstart + chunk * BK + c * 8;
                }
            } else {
                if (g < 1024) {
                    row = g >> 2; c = g & 3;
                    base = Ah;
                    dst = sb + sw_off(row, c);
                    base += (size_t)(bm + row) * K + kstart + chunk * BK + c * 8;
                } else {
                    int u = g - 1024;
                    row = u >> 2; c = u & 3;
                    base = Bh;
                    dst = sb + 2 * ATILE_B + sw_off(row, c);
                    base += (size_t)(bn + row) * K + kstart + chunk * BK + c * 8;
                }
            }
            asm volatile("cp.async.cg.shared.global [%0], [%1], 16;" :: "r"(dst), "l"(base));
        }
        asm volatile("cp.async.commit_group;" ::: "memory");
    };

    #pragma unroll
    for (int p = 0; p < 3; p++) {
        if (p < NC) load_chunk(p);
        else asm volatile("cp.async.commit_group;" ::: "memory");
    }

    for (int i = 0; i < NC; i++) {
        asm volatile("cp.async.wait_group 2;" ::: "memory");
        __syncthreads();
        if (i + 3 < NC) load_chunk(i + 3);
        else asm volatile("cp.async.commit_group;" ::: "memory");

        const uint32_t sb  = sbase + (i % STAGES) * STAGE_B;
        const uint32_t sAh = sb;
        const uint32_t sAl = sb + ATILE_B;
        const uint32_t sBh = sb + 2 * ATILE_B;
        const uint32_t sBl = sb + 2 * ATILE_B + BTILE_B;
        const int q = lane >> 3, r = lane & 7;

        #pragma unroll
        for (int ks = 0; ks < 2; ks++) {
            uint32_t a_h[2][4], a_l[2][4];
            #pragma unroll
            for (int mf = 0; mf < 2; mf++) {
                int row = wm * 32 + mf * 16 + ((q & 1) << 3) + r;
                int ch  = 2 * ks + (q >> 1);
                uint32_t ad = sw_off(row, ch);
                ldsm_x4(a_h[mf][0], a_h[mf][1], a_h[mf][2], a_h[mf][3], sAh + ad);
                if (NPASS == 3)
                    ldsm_x4(a_l[mf][0], a_l[mf][1], a_l[mf][2], a_l[mf][3], sAl + ad);
            }
            #pragma unroll
            for (int np = 0; np < 4; np++) {
                uint32_t b_h[2][2], b_l[2][2];
                int row = wn * 64 + np * 16 + ((q >> 1) << 3) + r;
                int ch  = 2 * ks + (q & 1);
                uint32_t bd = sw_off(row, ch);
                ldsm_x4(b_h[0][0], b_h[0][1], b_h[1][0], b_h[1][1], sBh + bd);
                if (NPASS == 3)
                    ldsm_x4(b_l[0][0], b_l[0][1], b_l[1][0], b_l[1][1], sBl + bd);
                #pragma unroll
                for (int mf = 0; mf < 2; mf++)
                    #pragma unroll
                    for (int nn = 0; nn < 2; nn++) {
                        float* d = acc[mf][2 * np + nn];
                        mma16816(d, a_h[mf], b_h[nn]);
                        if (NPASS == 3) {
                            mma16816(d, a_h[mf], b_l[nn]);
                            mma16816(d, a_l[mf], b_h[nn]);
                        }
                    }
            }
        }
    }
    __syncthreads();

    // ---- epilogue: fragment direct stores ----
    const int lr = lane >> 2;
    const int lc = (lane & 3) * 2;
    #pragma unroll
    for (int mf = 0; mf < 2; mf++) {
        #pragma unroll
        for (int nf = 0; nf < 8; nf++) {
            int row0 = bm + wm * 32 + mf * 16 + lr;
            int col  = bn + wn * 64 + nf * 8 + lc;
            float* d = acc[mf][nf];
            if (Cf) {
                *(float2*)&Cf[(size_t)row0 * N + col]       = make_float2(d[0], d[1]);
                *(float2*)&Cf[(size_t)(row0 + 8) * N + col] = make_float2(d[2], d[3]);
            } else {
                __half h0, l0, h1, l1;
                split_h(d[0], h0, l0); split_h(d[1], h1, l1);
                *(__half2*)&Ch[(size_t)row0 * N + col] = __halves2half2(h0, h1);
                *(__half2*)&Cl[(size_t)row0 * N + col] = __halves2half2(l0, l1);
                split_h(d[2], h0, l0); split_h(d[3], h1, l1);
                *(__half2*)&Ch[(size_t)(row0 + 8) * N + col] = __halves2half2(h0, h1);
                *(__half2*)&Cl[(size_t)(row0 + 8) * N + col] = __halves2half2(l0, l1);
            }
        }
    }
}

// ---------------- row softmax over SEQ=4096 -> plain fp16 weights ----------------
__global__ void __launch_bounds__(256) softmax_kernel(const float* __restrict__ sc,
                                                      __half* __restrict__ wh)
{
    const size_t row = blockIdx.x;
    const float* p = sc + row * (size_t)SEQ;
    const int tid = threadIdx.x;

    float4 v[4];
    float m = -CUDART_INF_F;
    #pragma unroll
    for (int i = 0; i < 4; i++) {
        v[i] = *(const float4*)(p + (size_t)i * 1024 + tid * 4);
        m = fmaxf(m, fmaxf(fmaxf(v[i].x, v[i].y), fmaxf(v[i].z, v[i].w)));
    }

    __shared__ float sred[8];
    #pragma unroll
    for (int o = 16; o > 0; o >>= 1) m = fmaxf(m, __shfl_xor_sync(0xffffffffu, m, o));
    if ((tid & 31) == 0) sred[tid >> 5] = m;
    __syncthreads();
    float rmax = sred[0];
    #pragma unroll
    for (int i = 1; i < 8; i++) rmax = fmaxf(rmax, sred[i]);
    __syncthreads();

    float s = 0.0f;
    #pragma unroll
    for (int i = 0; i < 4; i++) {
        v[i].x = expf(v[i].x - rmax);
        v[i].y = expf(v[i].y - rmax);
        v[i].z = expf(v[i].z - rmax);
        v[i].w = expf(v[i].w - rmax);
        s += (v[i].x + v[i].y) + (v[i].z + v[i].w);
    }
    #pragma unroll
    for (int o = 16; o > 0; o >>= 1) s += __shfl_xor_sync(0xffffffffu, s, o);
    if ((tid & 31) == 0) sred[tid >> 5] = s;
    __syncthreads();
    float rsum = 0.0f;
    #pragma unroll
    for (int i = 0; i < 8; i++) rsum += sred[i];

    const float inv = 1.0f / rsum;
    __half* oh = wh + row * (size_t)SEQ;
    #pragma unroll
    for (int i = 0; i < 4; i++) {
        __half h0 = __float2half_rn(v[i].x * inv);
        __half h1 = __float2half_rn(v[i].y * inv);
        __half h2 = __float2half_rn(v[i].z * inv);
        __half h3 = __float2half_rn(v[i].w * inv);
        size_t idx = (size_t)i * 1024 + tid * 4;
        *(__half2*)&oh[idx]     = __halves2half2(h0, h1);
        *(__half2*)&oh[idx + 2] = __halves2half2(h2, h3);
    }
}

// ---------------- launch: serial chain + ONE overlap (softmax_b0 under scores_b1) --
extern "C" void kernel_launch(void* const* d_in, const int* in_sizes, int n_in,
                              void* d_out, int out_size)
{
    const float* query = (const float*)d_in[0];
    const float* key   = (const float*)d_in[1];
    const float* Wq    = (const float*)d_in[2];
    const float* Wk    = (const float*)d_in[3];
    float* out = (float*)d_out;

    __half *qry_h, *qry_l, *key_h, *key_l, *wq_h, *wq_l, *wk_h, *wk_l;
    __half *mt_h, *mt_l, *keyT_h, *keyT_l, *qm_h, *qm_l, *w_h;
    float *sc, *mt_part;
    cudaGetSymbolAddress((void**)&qry_h,   g_qry_h);
    cudaGetSymbolAddress((void**)&qry_l,   g_qry_l);
    cudaGetSymbolAddress((void**)&key_h,   g_key_h);
    cudaGetSymbolAddress((void**)&key_l,   g_key_l);
    cudaGetSymbolAddress((void**)&wq_h,    g_wq_h);
    cudaGetSymbolAddress((void**)&wq_l,    g_wq_l);
    cudaGetSymbolAddress((void**)&wk_h,    g_wk_h);
    cudaGetSymbolAddress((void**)&wk_l,    g_wk_l);
    cudaGetSymbolAddress((void**)&mt_part, g_mt_part);
    cudaGetSymbolAddress((void**)&mt_h,    g_mt_h);
    cudaGetSymbolAddress((void**)&mt_l,    g_mt_l);
    cudaGetSymbolAddress((void**)&keyT_h,  g_keyT_h);
    cudaGetSymbolAddress((void**)&keyT_l,  g_keyT_l);
    cudaGetSymbolAddress((void**)&qm_h,    g_qm_h);
    cudaGetSymbolAddress((void**)&qm_l,    g_qm_l);
    cudaGetSymbolAddress((void**)&sc,      g_sc);
    cudaGetSymbolAddress((void**)&w_h,     g_w_h);

    cudaFuncSetAttribute(gemm_mma<3, 1>, cudaFuncAttributeMaxDynamicSharedMemorySize, DYN_SMEM);
    cudaFuncSetAttribute(gemm_mma<1, 1>, cudaFuncAttributeMaxDynamicSharedMemorySize, DYN_SMEM);
    cudaFuncSetAttribute(gemm_mma<3, MT_SPLITK>, cudaFuncAttributeMaxDynamicSharedMemorySize, DYN_SMEM);

    // one-time side-stream + events (resources only; identical DAG every call)
    static cudaStream_t s1 = nullptr;
    static cudaEvent_t evSc0, evSm0;
    if (!s1) {
        cudaStreamCreateWithFlags(&s1, cudaStreamNonBlocking);
        cudaEventCreateWithFlags(&evSc0, cudaEventDisableTiming);
        cudaEventCreateWithFlags(&evSm0, cudaEventDisableTiming);
    }
    cudaStream_t d = 0;

    const long long sQK = (long long)SEQ * DIM;
    const long long sSC = (long long)SEQ * SEQ;
    const long long sKT = (long long)DIM * SEQ;
    const size_t n4qk = (size_t)BATCH * SEQ * DIM / 4;
    const size_t n4w  = (size_t)DIM * DIM / 4;
    const size_t nMt  = (size_t)DIM * DIM;

    // 1) splits: query (grid.y=1) and Wq+Wk (grid.y=2)
    split2_kernel<<<dim3(2048, 1), 256, 0, d>>>(query, qry_h, qry_l, nullptr, nullptr, nullptr, n4qk);
    split2_kernel<<<dim3(256, 2), 256, 0, d>>>(Wq, wq_h, wq_l, Wk, wk_h, wk_l, n4w);

    // 2) fused key prep: straight split + transposed split in one pass
    transpose_split_plus_kernel<<<dim3(DIM / 32, SEQ / 32, BATCH), dim3(32, 8), 0, d>>>(
        key, keyT_h, keyT_l, key_h, key_l, SEQ, DIM, sQK, sKT, sQK);

    // 3) Mt = Wk @ Wq^T (16-way split-K) then reduce+split
    gemm_mma<3, MT_SPLITK><<<dim3(DIM / BN, DIM / BM, MT_SPLITK), NTHREADS, DYN_SMEM, d>>>(
        wk_h, wk_l, wq_h, wq_l, mt_part, nullptr, nullptr, DIM, DIM, DIM, 0, 0, 0);
    reduce_split_kernel<<<256, 256, 0, d>>>(mt_part, mt_h, mt_l, nMt, nMt / 4);

    // 4) qm = query @ M
    gemm_mma<3><<<dim3(DIM / BN, SEQ / BM, BATCH), NTHREADS, DYN_SMEM, d>>>(
        qry_h, qry_l, mt_h, mt_l, nullptr, qm_h, qm_l, SEQ, DIM, DIM, sQK, 0, sQK);

    // 5) scores per batch; softmax_b0 overlaps scores_b1's tail waves on s1
    gemm_mma<3><<<dim3(SEQ / BN, SEQ / BM, 1), NTHREADS, DYN_SMEM, d>>>(
        qm_h, qm_l, key_h, key_l, sc, nullptr, nullptr, SEQ, SEQ, DIM, 0, 0, 0);
    cudaEventRecord(evSc0, d);
    gemm_mma<3><<<dim3(SEQ / BN, SEQ / BM, 1), NTHREADS, DYN_SMEM, d>>>(
        qm_h + sQK, qm_l + sQK, key_h + sQK, key_l + sQK, sc + sSC, nullptr, nullptr,
        SEQ, SEQ, DIM, 0, 0, 0);

    cudaStreamWaitEvent(s1, evSc0, 0);
    softmax_kernel<<<SEQ, 256, 0, s1>>>(sc, w_h);
    cudaEventRecord(evSm0, s1);

    // 6) softmax_b1 in-stream after scores_b1
    softmax_kernel<<<SEQ, 256, 0, d>>>(sc + sSC, w_h + sSC);

    // 7) out = weights @ key (both batches, one wave); joins s1 via evSm0
    cudaStreamWaitEvent(d, evSm0, 0);
    gemm_mma<1><<<dim3(DIM / BN, SEQ / BM, BATCH), NTHREADS, DYN_SMEM, d>>>(
        w_h, nullptr, keyT_h, nullptr, out, nullptr, nullptr, SEQ, DIM, SEQ, sSC, sKT, sQK);
}

// round 16
// speedup vs baseline: 1.0542x; 1.0542x over previous
#include <cuda_runtime.h>
#include <cuda_fp16.h>
#include <math_constants.h>
#include <cstdint>
#include <cstddef>

#define BATCH 2
#define SEQ   4096
#define DIM   512
#define MT_SPLITK 16

// ---------------- scratch (allocation-free: __device__ globals) ----------------
__device__ __half g_qry_h[(size_t)BATCH * SEQ * DIM];
__device__ __half g_qry_l[(size_t)BATCH * SEQ * DIM];
__device__ __half g_key_h[(size_t)BATCH * SEQ * DIM];
__device__ __half g_key_l[(size_t)BATCH * SEQ * DIM];
__device__ __half g_wq_h[(size_t)DIM * DIM];
__device__ __half g_wq_l[(size_t)DIM * DIM];
__device__ __half g_wk_h[(size_t)DIM * DIM];
__device__ __half g_wk_l[(size_t)DIM * DIM];
__device__ float  g_mt_part[(size_t)MT_SPLITK * DIM * DIM];   // split-K partials
__device__ __half g_mt_h[(size_t)DIM * DIM];
__device__ __half g_mt_l[(size_t)DIM * DIM];
__device__ __half g_keyT_h[(size_t)BATCH * DIM * SEQ];
__device__ __half g_keyT_l[(size_t)BATCH * DIM * SEQ];
__device__ __half g_qm_h[(size_t)BATCH * SEQ * DIM];
__device__ __half g_qm_l[(size_t)BATCH * SEQ * DIM];
__device__ float  g_sc [(size_t)BATCH * SEQ * SEQ];
__device__ __half g_w_h[(size_t)BATCH * SEQ * SEQ];

// ---------------- helpers ----------------
__device__ __forceinline__ uint32_t s2u(const void* p) {
    uint32_t a;
    asm("{ .reg .u64 t; cvta.to.shared.u64 t, %1; cvt.u32.u64 %0, t; }" : "=r"(a) : "l"(p));
    return a;
}

__device__ __forceinline__ void ldsm_x4(uint32_t& r0, uint32_t& r1, uint32_t& r2, uint32_t& r3,
                                        uint32_t addr) {
    asm volatile("ldmatrix.sync.aligned.m8n8.x4.shared.b16 {%0,%1,%2,%3}, [%4];"
                 : "=r"(r0), "=r"(r1), "=r"(r2), "=r"(r3) : "r"(addr));
}

__device__ __forceinline__ void mma16816(float* d, const uint32_t* a, const uint32_t* b) {
    asm volatile(
        "mma.sync.aligned.m16n8k16.row.col.f32.f16.f16.f32 "
        "{%0,%1,%2,%3},{%4,%5,%6,%7},{%8,%9},{%0,%1,%2,%3};"
        : "+f"(d[0]), "+f"(d[1]), "+f"(d[2]), "+f"(d[3])
        : "r"(a[0]), "r"(a[1]), "r"(a[2]), "r"(a[3]), "r"(b[0]), "r"(b[1]));
}

__device__ __forceinline__ void split_h(float v, __half& h, __half& l) {
    h = __float2half_rn(v);
    l = __float2half_rn(v - __half2float(h));
}

// ---------------- prep kernels ----------------
// Fused, vectorized split of up to three tensors: grid.y selects tensor.
// Per-tensor element counts differ; surplus CTAs exit via the loop bound.
__global__ void __launch_bounds__(256) split3_kernel(
    const float* __restrict__ in0, __half* __restrict__ oh0, __half* __restrict__ ol0, size_t n40,
    const float* __restrict__ in1, __half* __restrict__ oh1, __half* __restrict__ ol1, size_t n41,
    const float* __restrict__ in2, __half* __restrict__ oh2, __half* __restrict__ ol2, size_t n42)
{
    const float* in; __half* oh; __half* ol; size_t n4;
    if (blockIdx.y == 0)      { in = in0; oh = oh0; ol = ol0; n4 = n40; }
    else if (blockIdx.y == 1) { in = in1; oh = oh1; ol = ol1; n4 = n41; }
    else                      { in = in2; oh = oh2; ol = ol2; n4 = n42; }
    for (size_t i = (size_t)blockIdx.x * blockDim.x + threadIdx.x; i < n4;
         i += (size_t)gridDim.x * blockDim.x) {
        float4 v = *(const float4*)(in + i * 4);
        __half h0, l0, h1, l1, h2, l2, h3, l3;
        split_h(v.x, h0, l0); split_h(v.y, h1, l1);
        split_h(v.z, h2, l2); split_h(v.w, h3, l3);
        *(__half2*)(oh + i * 4)     = __halves2half2(h0, h1);
        *(__half2*)(oh + i * 4 + 2) = __halves2half2(h2, h3);
        *(__half2*)(ol + i * 4)     = __halves2half2(l0, l1);
        *(__half2*)(ol + i * 4 + 2) = __halves2half2(l2, l3);
    }
}

// sum MT_SPLITK fp32 partials -> exact fp16 split (vectorized by float4)
__global__ void __launch_bounds__(256) reduce_split_kernel(
    const float* __restrict__ part, __half* __restrict__ oh, __half* __restrict__ ol,
    size_t n, size_t n4)
{
    for (size_t i = (size_t)blockIdx.x * blockDim.x + threadIdx.x; i < n4;
         i += (size_t)gridDim.x * blockDim.x) {
        float4 s = *(const float4*)(part + i * 4);
        #pragma unroll
        for (int k = 1; k < MT_SPLITK; k++) {
            float4 v = *(const float4*)(part + (size_t)k * n + i * 4);
            s.x += v.x; s.y += v.y; s.z += v.z; s.w += v.w;
        }
        __half h0, l0, h1, l1, h2, l2, h3, l3;
        split_h(s.x, h0, l0); split_h(s.y, h1, l1);
        split_h(s.z, h2, l2); split_h(s.w, h3, l3);
        *(__half2*)(oh + i * 4)     = __halves2half2(h0, h1);
        *(__half2*)(oh + i * 4 + 2) = __halves2half2(h2, h3);
        *(__half2*)(ol + i * 4)     = __halves2half2(l0, l1);
        *(__half2*)(ol + i * 4 + 2) = __halves2half2(l2, l3);
    }
}

// Fused key prep: emits BOTH the straight split (sh/sl, [R,C]) and the
// transposed split (oh/ol, [C,R]) in one pass over the input.
__global__ void transpose_split_plus_kernel(
    const float* __restrict__ in,
    __half* __restrict__ oh, __half* __restrict__ ol,   // transposed [C,R]
    __half* __restrict__ sh, __half* __restrict__ sl,   // straight  [R,C]
    int R, int C, long long sIn, long long sOutT, long long sOutS)
{
    __shared__ float t[32][33];
    const int bz = blockIdx.z;
    in += (size_t)bz * sIn;
    oh += (size_t)bz * sOutT;
    ol += (size_t)bz * sOutT;
    sh += (size_t)bz * sOutS;
    sl += (size_t)bz * sOutS;
    const int c0 = blockIdx.x * 32, r0 = blockIdx.y * 32;
    const int tx = threadIdx.x, ty = threadIdx.y;  // 32 x 8
    #pragma unroll
    for (int j = 0; j < 32; j += 8) {
        size_t sidx = (size_t)(r0 + ty + j) * C + c0 + tx;
        float v = in[sidx];
        t[ty + j][tx] = v;
        __half h, l; split_h(v, h, l);
        sh[sidx] = h; sl[sidx] = l;              // coalesced along tx
    }
    __syncthreads();
    #pragma unroll
    for (int j = 0; j < 32; j += 8) {
        size_t idx = (size_t)(c0 + ty + j) * R + r0 + tx;
        __half h, l; split_h(t[tx][ty + j], h, l);
        oh[idx] = h; ol[idx] = l;
    }
}

// ---------------- mma.sync fp16 GEMM:  C[M,N] = A[M,K] * B[N,K]^T -------------
#define BM 256
#define BN 128
#define BK 32
#define STAGES 4
#define ATILE_B (BM * BK * 2)
#define BTILE_B (BN * BK * 2)
#define STAGE_B (2 * ATILE_B + 2 * BTILE_B)   // 48 KB
#define DYN_SMEM (STAGES * STAGE_B)           // 192 KB
#define NTHREADS 512

__device__ __forceinline__ uint32_t sw_off(int row, int ch) {
    return (uint32_t)(row * 64 + ((ch ^ ((row >> 1) & 3)) << 4));
}

template <int NPASS, int SPLITK = 1>
__global__ void __launch_bounds__(NTHREADS, 1) gemm_mma(
    const __half* __restrict__ Ah, const __half* __restrict__ Al,
    const __half* __restrict__ Bh, const __half* __restrict__ Bl,
    float* __restrict__ Cf, __half* __restrict__ Ch, __half* __restrict__ Cl,
    int M, int N, int K, long long sA, long long sB, long long sC)
{
    extern __shared__ char smem[];
    const int tid  = threadIdx.x;
    const int lane = tid & 31;
    const int wid  = tid >> 5;
    const int wm   = wid & 7;
    const int wn   = wid >> 3;
    const int bz = blockIdx.z;
    int kstart, klen;
    if (SPLITK > 1) {
        kstart = bz * (K / SPLITK);
        klen   = K / SPLITK;
        Cf += (size_t)bz * M * N;
    } else {
        kstart = 0;
        klen   = K;
        Ah += (size_t)bz * sA;
        Bh += (size_t)bz * sB;
        if (NPASS == 3) { Al += (size_t)bz * sA; Bl += (size_t)bz * sB; }
        if (Cf) Cf += (size_t)bz * sC;
        if (Ch) { Ch += (size_t)bz * sC; Cl += (size_t)bz * sC; }
    }
    const int bm = blockIdx.y * BM;
    const int bn = blockIdx.x * BN;
    const uint32_t sbase = s2u(smem);
    const int NC = klen / BK;

    float acc[2][8][4];
    #pragma unroll
    for (int a = 0; a < 2; a++)
        #pragma unroll
        for (int b = 0; b < 8; b++)
            #pragma unroll
            for (int c = 0; c < 4; c++) acc[a][b][c] = 0.0f;

    auto load_chunk = [&](int chunk) {
        const uint32_t sb = sbase + (chunk % STAGES) * STAGE_B;
        constexpr int J = (NPASS == 3) ? 6 : 3;
        #pragma unroll
        for (int j = 0; j < J; j++) {
            int g = tid + NTHREADS * j;
            const __half* base;
            uint32_t dst;
            int row, c;
            if (NPASS == 3) {
                if (g < 2048) {
                    int t = g >> 10;
                    int u = g & 1023;
                    row = u >> 2; c = u & 3;
                    base = t ? Al : Ah;
                    dst = sb + t * ATILE_B + sw_off(row, c);
                    base += (size_t)(bm + row) * K + kstart + chunk * BK + c * 8;
                } else {
                    int b2 = g - 2048;
                    int t = b2 >> 9;
                    int u = b2 & 511;
                    row = u >> 2; c = u & 3;
                    base = t ? Bl : Bh;
                    dst = sb + 2 * ATILE_B + t * BTILE_B + sw_off(row, c);
                    base += (size_t)(bn + row) * K + kstart + chunk * BK + c * 8;
                }
            } else {
                if (g < 1024) {
                    row = g >> 2; c = g & 3;
                    base = Ah;
                    dst = sb + sw_off(row, c);
                    base += (size_t)(bm + row) * K + kstart + chunk * BK + c * 8;
                } else {
                    int u = g - 1024;
                    row = u >> 2; c = u & 3;
                    base = Bh;
                    dst = sb + 2 * ATILE_B + sw_off(row, c);
                    base += (size_t)(bn + row) * K + kstart + chunk * BK + c * 8;
                }
            }
            asm volatile("cp.async.cg.shared.global [%0], [%1], 16;" :: "r"(dst), "l"(base));
        }
        asm volatile("cp.async.commit_group;" ::: "memory");
    };

    #pragma unroll
    for (int p = 0; p < 3; p++) {
        if (p < NC) load_chunk(p);
        else asm volatile("cp.async.commit_group;" ::: "memory");
    }

    for (int i = 0; i < NC; i++) {
        asm volatile("cp.async.wait_group 2;" ::: "memory");
        __syncthreads();
        if (i + 3 < NC) load_chunk(i + 3);
        else asm volatile("cp.async.commit_group;" ::: "memory");

        const uint32_t sb  = sbase + (i % STAGES) * STAGE_B;
        const uint32_t sAh = sb;
        const uint32_t sAl = sb + ATILE_B;
        const uint32_t sBh = sb + 2 * ATILE_B;
        const uint32_t sBl = sb + 2 * ATILE_B + BTILE_B;
        const int q = lane >> 3, r = lane & 7;

        #pragma unroll
        for (int ks = 0; ks < 2; ks++) {
            uint32_t a_h[2][4], a_l[2][4];
            #pragma unroll
            for (int mf = 0; mf < 2; mf++) {
                int row = wm * 32 + mf * 16 + ((q & 1) << 3) + r;
                int ch  = 2 * ks + (q >> 1);
                uint32_t ad = sw_off(row, ch);
                ldsm_x4(a_h[mf][0], a_h[mf][1], a_h[mf][2], a_h[mf][3], sAh + ad);
                if (NPASS == 3)
                    ldsm_x4(a_l[mf][0], a_l[mf][1], a_l[mf][2], a_l[mf][3], sAl + ad);
            }
            #pragma unroll
            for (int np = 0; np < 4; np++) {
                uint32_t b_h[2][2], b_l[2][2];
                int row = wn * 64 + np * 16 + ((q >> 1) << 3) + r;
                int ch  = 2 * ks + (q & 1);
                uint32_t bd = sw_off(row, ch);
                ldsm_x4(b_h[0][0], b_h[0][1], b_h[1][0], b_h[1][1], sBh + bd);
                if (NPASS == 3)
                    ldsm_x4(b_l[0][0], b_l[0][1], b_l[1][0], b_l[1][1], sBl + bd);
                #pragma unroll
                for (int mf = 0; mf < 2; mf++)
                    #pragma unroll
                    for (int nn = 0; nn < 2; nn++) {
                        float* d = acc[mf][2 * np + nn];
                        mma16816(d, a_h[mf], b_h[nn]);
                        if (NPASS == 3) {
                            mma16816(d, a_h[mf], b_l[nn]);
                            mma16816(d, a_l[mf], b_h[nn]);
                        }
                    }
            }
        }
    }
    __syncthreads();

    // ---- epilogue: fragment direct stores ----
    const int lr = lane >> 2;
    const int lc = (lane & 3) * 2;
    #pragma unroll
    for (int mf = 0; mf < 2; mf++) {
        #pragma unroll
        for (int nf = 0; nf < 8; nf++) {
            int row0 = bm + wm * 32 + mf * 16 + lr;
            int col  = bn + wn * 64 + nf * 8 + lc;
            float* d = acc[mf][nf];
            if (Cf) {
                *(float2*)&Cf[(size_t)row0 * N + col]       = make_float2(d[0], d[1]);
                *(float2*)&Cf[(size_t)(row0 + 8) * N + col] = make_float2(d[2], d[3]);
            } else {
                __half h0, l0, h1, l1;
                split_h(d[0], h0, l0); split_h(d[1], h1, l1);
                *(__half2*)&Ch[(size_t)row0 * N + col] = __halves2half2(h0, h1);
                *(__half2*)&Cl[(size_t)row0 * N + col] = __halves2half2(l0, l1);
                split_h(d[2], h0, l0); split_h(d[3], h1, l1);
                *(__half2*)&Ch[(size_t)(row0 + 8) * N + col] = __halves2half2(h0, h1);
                *(__half2*)&Cl[(size_t)(row0 + 8) * N + col] = __halves2half2(l0, l1);
            }
        }
    }
}

// ---------------- row softmax over SEQ=4096 -> plain fp16 weights ----------------
__global__ void __launch_bounds__(256) softmax_kernel(const float* __restrict__ sc,
                                                      __half* __restrict__ wh)
{
    const size_t row = blockIdx.x;
    const float* p = sc + row * (size_t)SEQ;
    const int tid = threadIdx.x;

    float4 v[4];
    float m = -CUDART_INF_F;
    #pragma unroll
    for (int i = 0; i < 4; i++) {
        v[i] = *(const float4*)(p + (size_t)i * 1024 + tid * 4);
        m = fmaxf(m, fmaxf(fmaxf(v[i].x, v[i].y), fmaxf(v[i].z, v[i].w)));
    }

    __shared__ float sred[8];
    #pragma unroll
    for (int o = 16; o > 0; o >>= 1) m = fmaxf(m, __shfl_xor_sync(0xffffffffu, m, o));
    if ((tid & 31) == 0) sred[tid >> 5] = m;
    __syncthreads();
    float rmax = sred[0];
    #pragma unroll
    for (int i = 1; i < 8; i++) rmax = fmaxf(rmax, sred[i]);
    __syncthreads();

    float s = 0.0f;
    #pragma unroll
    for (int i = 0; i < 4; i++) {
        v[i].x = expf(v[i].x - rmax);
        v[i].y = expf(v[i].y - rmax);
        v[i].z = expf(v[i].z - rmax);
        v[i].w = expf(v[i].w - rmax);
        s += (v[i].x + v[i].y) + (v[i].z + v[i].w);
    }
    #pragma unroll
    for (int o = 16; o > 0; o >>= 1) s += __shfl_xor_sync(0xffffffffu, s, o);
    if ((tid & 31) == 0) sred[tid >> 5] = s;
    __syncthreads();
    float rsum = 0.0f;
    #pragma unroll
    for (int i = 0; i < 8; i++) rsum += sred[i];

    const float inv = 1.0f / rsum;
    __half* oh = wh + row * (size_t)SEQ;
    #pragma unroll
    for (int i = 0; i < 4; i++) {
        __half h0 = __float2half_rn(v[i].x * inv);
        __half h1 = __float2half_rn(v[i].y * inv);
        __half h2 = __float2half_rn(v[i].z * inv);
        __half h3 = __float2half_rn(v[i].w * inv);
        size_t idx = (size_t)i * 1024 + tid * 4;
        *(__half2*)&oh[idx]     = __halves2half2(h0, h1);
        *(__half2*)&oh[idx + 2] = __halves2half2(h2, h3);
    }
}

// ---------------- launch (single stream; R14 schedule, merged splits) ----------
extern "C" void kernel_launch(void* const* d_in, const int* in_sizes, int n_in,
                              void* d_out, int out_size)
{
    const float* query = (const float*)d_in[0];
    const float* key   = (const float*)d_in[1];
    const float* Wq    = (const float*)d_in[2];
    const float* Wk    = (const float*)d_in[3];
    float* out = (float*)d_out;

    __half *qry_h, *qry_l, *key_h, *key_l, *wq_h, *wq_l, *wk_h, *wk_l;
    __half *mt_h, *mt_l, *keyT_h, *keyT_l, *qm_h, *qm_l, *w_h;
    float *sc, *mt_part;
    cudaGetSymbolAddress((void**)&qry_h,   g_qry_h);
    cudaGetSymbolAddress((void**)&qry_l,   g_qry_l);
    cudaGetSymbolAddress((void**)&key_h,   g_key_h);
    cudaGetSymbolAddress((void**)&key_l,   g_key_l);
    cudaGetSymbolAddress((void**)&wq_h,    g_wq_h);
    cudaGetSymbolAddress((void**)&wq_l,    g_wq_l);
    cudaGetSymbolAddress((void**)&wk_h,    g_wk_h);
    cudaGetSymbolAddress((void**)&wk_l,    g_wk_l);
    cudaGetSymbolAddress((void**)&mt_part, g_mt_part);
    cudaGetSymbolAddress((void**)&mt_h,    g_mt_h);
    cudaGetSymbolAddress((void**)&mt_l,    g_mt_l);
    cudaGetSymbolAddress((void**)&keyT_h,  g_keyT_h);
    cudaGetSymbolAddress((void**)&keyT_l,  g_keyT_l);
    cudaGetSymbolAddress((void**)&qm_h,    g_qm_h);
    cudaGetSymbolAddress((void**)&qm_l,    g_qm_l);
    cudaGetSymbolAddress((void**)&sc,      g_sc);
    cudaGetSymbolAddress((void**)&w_h,     g_w_h);

    cudaFuncSetAttribute(gemm_mma<3, 1>, cudaFuncAttributeMaxDynamicSharedMemorySize, DYN_SMEM);
    cudaFuncSetAttribute(gemm_mma<1, 1>, cudaFuncAttributeMaxDynamicSharedMemorySize, DYN_SMEM);
    cudaFuncSetAttribute(gemm_mma<3, MT_SPLITK>, cudaFuncAttributeMaxDynamicSharedMemorySize, DYN_SMEM);

    const long long sQK = (long long)SEQ * DIM;
    const long long sSC = (long long)SEQ * SEQ;
    const long long sKT = (long long)DIM * SEQ;
    const size_t n4qk = (size_t)BATCH * SEQ * DIM / 4;
    const size_t n4w  = (size_t)DIM * DIM / 4;
    const size_t nMt  = (size_t)DIM * DIM;

    // 1) one launch splits query + Wq + Wk (grid.y selects tensor)
    split3_kernel<<<dim3(2048, 3), 256>>>(
        query, qry_h, qry_l, n4qk,
        Wq,    wq_h,  wq_l,  n4w,
        Wk,    wk_h,  wk_l,  n4w);

    // 2) fused key prep: straight split + transposed split in one pass
    transpose_split_plus_kernel<<<dim3(DIM / 32, SEQ / 32, BATCH), dim3(32, 8)>>>(
        key, keyT_h, keyT_l, key_h, key_l, SEQ, DIM, sQK, sKT, sQK);

    // 3) Mt = Wk @ Wq^T (16-way split-K) then reduce+split
    gemm_mma<3, MT_SPLITK><<<dim3(DIM / BN, DIM / BM, MT_SPLITK), NTHREADS, DYN_SMEM>>>(
        wk_h, wk_l, wq_h, wq_l, mt_part, nullptr, nullptr, DIM, DIM, DIM, 0, 0, 0);
    reduce_split_kernel<<<256, 256>>>(mt_part, mt_h, mt_l, nMt, nMt / 4);

    // 4) qm = query @ M  (single projection; scores = qm @ key^T)
    gemm_mma<3><<<dim3(DIM / BN, SEQ / BM, BATCH), NTHREADS, DYN_SMEM>>>(
        qry_h, qry_l, mt_h, mt_l, nullptr, qm_h, qm_l, SEQ, DIM, DIM, sQK, 0, sQK);

    // 5) scores = qm @ key^T (3-pass, fp32 out; single launch, grid.z = batch)
    gemm_mma<3><<<dim3(SEQ / BN, SEQ / BM, BATCH), NTHREADS, DYN_SMEM>>>(
        qm_h, qm_l, key_h, key_l, sc, nullptr, nullptr, SEQ, SEQ, DIM, sQK, sQK, sSC);

    // 6) softmax -> plain fp16 weights
    softmax_kernel<<<BATCH * SEQ, 256>>>(sc, w_h);

    // 7) out = weights @ key (1-pass plain fp16)
    gemm_mma<1><<<dim3(DIM / BN, SEQ / BM, BATCH), NTHREADS, DYN_SMEM>>>(
        w_h, nullptr, keyT_h, nullptr, out, nullptr, nullptr, SEQ, DIM, SEQ, sSC, sKT, sQK);
}